// round 1
// baseline (speedup 1.0000x reference)
#include <cuda_runtime.h>
#include <cuda_bf16.h>
#include <math.h>

#define N_NODES 100000
#define N_EDGES 3200000
#define F_IN    512
#define HID     256
#define NCLS    64
#define NLAYERS 8
#define ALPHA   0.1f

// ---------------- device scratch (static, no allocations) ----------------
__device__ float g_h[(size_t)N_NODES * HID];
__device__ float g_x0[(size_t)N_NODES * HID];
__device__ float g_mix[(size_t)N_NODES * HID];
__device__ int   g_rowptr[N_NODES + 1];
__device__ int   g_cnt[N_NODES];
__device__ int   g_colv[N_EDGES];
__device__ float g_valv[N_EDGES];

// ---------------- CSR build ----------------
__global__ void zero_cnt_kernel() {
    int i = blockIdx.x * blockDim.x + threadIdx.x;
    if (i < N_NODES) g_cnt[i] = 0;
}

__global__ void count_kernel(const int* __restrict__ edge_row) {
    int e = blockIdx.x * blockDim.x + threadIdx.x;
    if (e < N_EDGES) atomicAdd(&g_cnt[edge_row[e]], 1);
}

// single-block exclusive scan over N_NODES counts -> rowptr; zeroes g_cnt for reuse
__global__ void scan_kernel() {
    __shared__ int s[1024];
    const int t = threadIdx.x;
    const int CH = (N_NODES + 1023) / 1024;
    int begin = t * CH;
    int end = begin + CH; if (end > N_NODES) end = N_NODES;
    if (begin > N_NODES) begin = N_NODES;
    int sum = 0;
    for (int i = begin; i < end; i++) sum += g_cnt[i];
    s[t] = sum;
    __syncthreads();
    // Hillis-Steele inclusive scan
    for (int off = 1; off < 1024; off <<= 1) {
        int v = (t >= off) ? s[t - off] : 0;
        __syncthreads();
        s[t] += v;
        __syncthreads();
    }
    int run = s[t] - sum;  // exclusive prefix for this chunk
    for (int i = begin; i < end; i++) {
        int c = g_cnt[i];
        g_rowptr[i] = run;
        run += c;
        g_cnt[i] = 0;
    }
    if (t == 1023) g_rowptr[N_NODES] = s[1023];
}

__global__ void scatter_kernel(const int* __restrict__ edge_row,
                               const int* __restrict__ edge_col,
                               const float* __restrict__ edge_val) {
    int e = blockIdx.x * blockDim.x + threadIdx.x;
    if (e < N_EDGES) {
        int r = edge_row[e];
        int pos = g_rowptr[r] + atomicAdd(&g_cnt[r], 1);
        g_colv[pos] = edge_col[e];
        g_valv[pos] = edge_val[e];
    }
}

// ---------------- SpMM: mix = 0.9 * (A @ h) + 0.1 * x0 ----------------
// one warp per row, 8 features per lane (HID=256)
__global__ void spmm_kernel() {
    const int lane = threadIdx.x & 31;
    const int wid = threadIdx.x >> 5;
    const int row = blockIdx.x * (blockDim.x >> 5) + wid;
    if (row >= N_NODES) return;

    const int start = g_rowptr[row];
    const int end = g_rowptr[row + 1];

    float acc[8];
#pragma unroll
    for (int k = 0; k < 8; k++) acc[k] = 0.f;

    int e = start;
    for (; e + 1 < end; e += 2) {
        int c0 = g_colv[e];
        int c1 = g_colv[e + 1];
        float v0 = g_valv[e];
        float v1 = g_valv[e + 1];
        const float* f0 = g_h + (size_t)c0 * HID + lane;
        const float* f1 = g_h + (size_t)c1 * HID + lane;
#pragma unroll
        for (int k = 0; k < 8; k++) acc[k] += v0 * f0[32 * k];
#pragma unroll
        for (int k = 0; k < 8; k++) acc[k] += v1 * f1[32 * k];
    }
    if (e < end) {
        int c0 = g_colv[e];
        float v0 = g_valv[e];
        const float* f0 = g_h + (size_t)c0 * HID + lane;
#pragma unroll
        for (int k = 0; k < 8; k++) acc[k] += v0 * f0[32 * k];
    }

    float* out = g_mix + (size_t)row * HID + lane;
    const float* x0p = g_x0 + (size_t)row * HID + lane;
#pragma unroll
    for (int k = 0; k < 8; k++) {
        out[32 * k] = (1.f - ALPHA) * acc[k] + ALPHA * x0p[32 * k];
    }
}

// ---------------- dense GEMM (fp32, tiled) ----------------
// C[M,N] = epilogue(w_acc * (A[M,K] @ B[K,N]) + w_resid*resid + bias)
template <int BM, int BN, int BK, int TM, int TN>
__global__ __launch_bounds__((BM / TM) * (BN / TN))
void gemm_kernel(const float* __restrict__ A, const float* __restrict__ B,
                 float* __restrict__ C, float* __restrict__ C2,
                 int M, int N, int K,
                 const float* __restrict__ bias,
                 const float* __restrict__ resid,
                 float w_acc, float w_resid, int do_relu) {
    __shared__ float As[BK][BM + 4];
    __shared__ float Bs[BK][BN];

    constexpr int THREADS = (BM / TM) * (BN / TN);
    const int tid = threadIdx.x;
    const int blockRow = blockIdx.y;
    const int blockCol = blockIdx.x;

    const int tcol = tid % (BN / TN);
    const int trow = tid / (BN / TN);

    float acc[TM][TN];
#pragma unroll
    for (int i = 0; i < TM; i++)
#pragma unroll
        for (int j = 0; j < TN; j++) acc[i][j] = 0.f;

    constexpr int A_VEC_PER_ROW = BK / 4;
    const int aRow0 = tid / A_VEC_PER_ROW;
    const int aCol = (tid % A_VEC_PER_ROW) * 4;
    constexpr int A_ROW_STRIDE = THREADS / A_VEC_PER_ROW;

    constexpr int B_VEC_PER_ROW = BN / 4;
    const int bRow0 = tid / B_VEC_PER_ROW;
    const int bCol = (tid % B_VEC_PER_ROW) * 4;
    constexpr int B_ROW_STRIDE = THREADS / B_VEC_PER_ROW;

    const float* Abase = A + (size_t)blockRow * BM * K;
    const float* Bbase = B + (size_t)blockCol * BN;

    for (int k0 = 0; k0 < K; k0 += BK) {
#pragma unroll
        for (int r = 0; r < BM / A_ROW_STRIDE; r++) {
            int rr = aRow0 + r * A_ROW_STRIDE;
            int gRow = blockRow * BM + rr;
            float4 v = make_float4(0.f, 0.f, 0.f, 0.f);
            if (gRow < M)
                v = *(const float4*)(Abase + (size_t)rr * K + k0 + aCol);
            As[aCol + 0][rr] = v.x;
            As[aCol + 1][rr] = v.y;
            As[aCol + 2][rr] = v.z;
            As[aCol + 3][rr] = v.w;
        }
#pragma unroll
        for (int r = 0; r < BK / B_ROW_STRIDE; r++) {
            int rr = bRow0 + r * B_ROW_STRIDE;
            float4 v = *(const float4*)(Bbase + (size_t)(k0 + rr) * N + bCol);
            *(float4*)&Bs[rr][bCol] = v;
        }
        __syncthreads();

#pragma unroll
        for (int k = 0; k < BK; k++) {
            float a[TM], b[TN];
#pragma unroll
            for (int i = 0; i < TM; i++) a[i] = As[k][trow * TM + i];
#pragma unroll
            for (int j = 0; j < TN; j++) b[j] = Bs[k][tcol * TN + j];
#pragma unroll
            for (int i = 0; i < TM; i++)
#pragma unroll
                for (int j = 0; j < TN; j++) acc[i][j] += a[i] * b[j];
        }
        __syncthreads();
    }

#pragma unroll
    for (int i = 0; i < TM; i++) {
        int gr = blockRow * BM + trow * TM + i;
        if (gr >= M) continue;
#pragma unroll
        for (int j = 0; j < TN; j++) {
            int gc = blockCol * BN + tcol * TN + j;
            float v = w_acc * acc[i][j];
            if (resid) v += w_resid * resid[(size_t)gr * N + gc];
            if (bias) v += bias[gc];
            if (do_relu) v = fmaxf(v, 0.f);
            C[(size_t)gr * N + gc] = v;
            if (C2) C2[(size_t)gr * N + gc] = v;
        }
    }
}

// ---------------- log_softmax over last dim (C=64), in place ----------------
__global__ void logsoftmax_kernel(float* __restrict__ logits) {
    const int lane = threadIdx.x & 31;
    const int wid = threadIdx.x >> 5;
    const int row = blockIdx.x * (blockDim.x >> 5) + wid;
    if (row >= N_NODES) return;
    float* p = logits + (size_t)row * NCLS;
    float v0 = p[lane];
    float v1 = p[lane + 32];
    float m = fmaxf(v0, v1);
#pragma unroll
    for (int off = 16; off > 0; off >>= 1)
        m = fmaxf(m, __shfl_xor_sync(0xffffffffu, m, off));
    float s = expf(v0 - m) + expf(v1 - m);
#pragma unroll
    for (int off = 16; off > 0; off >>= 1)
        s += __shfl_xor_sync(0xffffffffu, s, off);
    float lse = m + logf(s);
    p[lane] = v0 - lse;
    p[lane + 32] = v1 - lse;
}

// ---------------- launch ----------------
extern "C" void kernel_launch(void* const* d_in, const int* in_sizes, int n_in,
                              void* d_out, int out_size) {
    const float* x        = (const float*)d_in[0];  // [N, F_IN]
    const float* edge_val = (const float*)d_in[1];  // [E]
    const float* W_in     = (const float*)d_in[2];  // [F_IN, H]
    const float* b_in     = (const float*)d_in[3];  // [H]
    const float* conv_W   = (const float*)d_in[4];  // [L, H, H]
    const float* W_out    = (const float*)d_in[5];  // [H, C]
    const float* b_out    = (const float*)d_in[6];  // [C]
    const int*   edge_row = (const int*)d_in[7];    // [E]
    const int*   edge_col = (const int*)d_in[8];    // [E]
    float* out = (float*)d_out;                      // [N, C]

    float *h_ptr, *x0_ptr, *mix_ptr;
    cudaGetSymbolAddress((void**)&h_ptr, g_h);
    cudaGetSymbolAddress((void**)&x0_ptr, g_x0);
    cudaGetSymbolAddress((void**)&mix_ptr, g_mix);

    // 1. CSR build
    zero_cnt_kernel<<<(N_NODES + 255) / 256, 256>>>();
    count_kernel<<<(N_EDGES + 255) / 256, 256>>>(edge_row);
    scan_kernel<<<1, 1024>>>();
    scatter_kernel<<<(N_EDGES + 255) / 256, 256>>>(edge_row, edge_col, edge_val);

    // 2. input GEMM: h = x0 = relu(x @ W_in + b_in)
    {
        dim3 grid(HID / 128, (N_NODES + 127) / 128);
        gemm_kernel<128, 128, 16, 8, 8><<<grid, 256>>>(
            x, W_in, h_ptr, x0_ptr, N_NODES, HID, F_IN,
            b_in, nullptr, 1.f, 0.f, 1);
    }

    // 3. GCN2 layers
    for (int l = 0; l < NLAYERS; l++) {
        float beta = (float)log(0.5 / (double)(l + 1) + 1.0);
        // mix = 0.9 * (A @ h) + 0.1 * x0
        spmm_kernel<<<(N_NODES + 7) / 8, 256>>>();
        // h = relu((1-beta)*mix + beta*(mix @ W_l))
        dim3 grid(HID / 128, (N_NODES + 127) / 128);
        gemm_kernel<128, 128, 16, 8, 8><<<grid, 256>>>(
            mix_ptr, conv_W + (size_t)l * HID * HID, h_ptr, nullptr,
            N_NODES, HID, HID,
            nullptr, mix_ptr, beta, 1.f - beta, 1);
    }

    // 4. output GEMM: logits = h @ W_out + b_out  (into d_out)
    {
        dim3 grid(NCLS / 64, (N_NODES + 127) / 128);
        gemm_kernel<128, 64, 16, 8, 4><<<grid, 256>>>(
            h_ptr, W_out, out, nullptr, N_NODES, NCLS, HID,
            b_out, nullptr, 1.f, 0.f, 0);
    }

    // 5. log_softmax in place
    logsoftmax_kernel<<<(N_NODES + 7) / 8, 256>>>(out);
}

// round 4
// speedup vs baseline: 1.5714x; 1.5714x over previous
#include <cuda_runtime.h>
#include <cuda_bf16.h>
#include <math.h>
#include <stdint.h>

#define N_NODES 100000
#define N_EDGES 3200000
#define F_IN    512
#define HID     256
#define NCLS    64
#define NLAYERS 8
#define ALPHA   0.1f

// ---------------- device scratch (static, no allocations) ----------------
__device__ float g_h[(size_t)N_NODES * HID];
__device__ float g_x0[(size_t)N_NODES * HID];
__device__ float g_mix[(size_t)N_NODES * HID];
__device__ __nv_bfloat16 g_mhi[(size_t)N_NODES * HID];
__device__ __nv_bfloat16 g_mlo[(size_t)N_NODES * HID];
__device__ __nv_bfloat16 g_xhi[(size_t)N_NODES * F_IN];
__device__ __nv_bfloat16 g_xlo[(size_t)N_NODES * F_IN];
__device__ __nv_bfloat16 g_Winhi[HID * F_IN];        // [n][k]
__device__ __nv_bfloat16 g_Winlo[HID * F_IN];
__device__ __nv_bfloat16 g_Wlhi[NLAYERS * HID * HID]; // [l][n][k]
__device__ __nv_bfloat16 g_Wllo[NLAYERS * HID * HID];
__device__ int   g_rowptr[N_NODES + 1];
__device__ int   g_cnt[N_NODES];
__device__ int   g_colv[N_EDGES];
__device__ float g_valv[N_EDGES];

// ---------------- PTX helpers (arch-agnostic: sm_80+) ----------------
__device__ __forceinline__ uint32_t smem_u32(const void* p) {
    uint32_t a;
    asm("{ .reg .u64 t; cvta.to.shared.u64 t, %1; cvt.u32.u64 %0, t; }" : "=r"(a) : "l"(p));
    return a;
}
__device__ __forceinline__ void cp_async16(uint32_t dst, const void* src) {
    asm volatile("cp.async.cg.shared.global [%0], [%1], 16;" :: "r"(dst), "l"(src));
}
#define CP_COMMIT() asm volatile("cp.async.commit_group;" ::: "memory")
#define CP_WAIT0()  asm volatile("cp.async.wait_group 0;" ::: "memory")

__device__ __forceinline__ void ldmx4(uint32_t* r, uint32_t addr) {
    asm volatile("ldmatrix.sync.aligned.m8n8.x4.shared.b16 {%0,%1,%2,%3}, [%4];"
                 : "=r"(r[0]), "=r"(r[1]), "=r"(r[2]), "=r"(r[3]) : "r"(addr));
}
__device__ __forceinline__ void ldmx2(uint32_t* r, uint32_t addr) {
    asm volatile("ldmatrix.sync.aligned.m8n8.x2.shared.b16 {%0,%1}, [%2];"
                 : "=r"(r[0]), "=r"(r[1]) : "r"(addr));
}
__device__ __forceinline__ void mma16816(float* d, const uint32_t* a, const uint32_t* b) {
    asm volatile("mma.sync.aligned.m16n8k16.row.col.f32.bf16.bf16.f32 "
                 "{%0,%1,%2,%3}, {%4,%5,%6,%7}, {%8,%9}, {%0,%1,%2,%3};"
                 : "+f"(d[0]), "+f"(d[1]), "+f"(d[2]), "+f"(d[3])
                 : "r"(a[0]), "r"(a[1]), "r"(a[2]), "r"(a[3]), "r"(b[0]), "r"(b[1]));
}

// ---------------- CSR build ----------------
__global__ void zero_cnt_kernel() {
    int i = blockIdx.x * blockDim.x + threadIdx.x;
    if (i < N_NODES) g_cnt[i] = 0;
}
__global__ void count_kernel(const int* __restrict__ edge_row) {
    int e = blockIdx.x * blockDim.x + threadIdx.x;
    if (e < N_EDGES) atomicAdd(&g_cnt[edge_row[e]], 1);
}
__global__ void scan_kernel() {
    __shared__ int s[1024];
    const int t = threadIdx.x;
    const int CH = (N_NODES + 1023) / 1024;
    int begin = t * CH;
    int end = begin + CH; if (end > N_NODES) end = N_NODES;
    if (begin > N_NODES) begin = N_NODES;
    int sum = 0;
    for (int i = begin; i < end; i++) sum += g_cnt[i];
    s[t] = sum;
    __syncthreads();
    for (int off = 1; off < 1024; off <<= 1) {
        int v = (t >= off) ? s[t - off] : 0;
        __syncthreads();
        s[t] += v;
        __syncthreads();
    }
    int run = s[t] - sum;
    for (int i = begin; i < end; i++) {
        int c = g_cnt[i];
        g_rowptr[i] = run;
        run += c;
        g_cnt[i] = 0;
    }
    if (t == 1023) g_rowptr[N_NODES] = s[1023];
}
__global__ void scatter_kernel(const int* __restrict__ edge_row,
                               const int* __restrict__ edge_col,
                               const float* __restrict__ edge_val) {
    int e = blockIdx.x * blockDim.x + threadIdx.x;
    if (e < N_EDGES) {
        int r = edge_row[e];
        int pos = g_rowptr[r] + atomicAdd(&g_cnt[r], 1);
        g_colv[pos] = edge_col[e];
        g_valv[pos] = edge_val[e];
    }
}

// ---------------- conversions ----------------
__device__ __forceinline__ void split_bf16(float v, __nv_bfloat16& hi, __nv_bfloat16& lo) {
    hi = __float2bfloat16_rn(v);
    lo = __float2bfloat16_rn(v - __bfloat162float(hi));
}

__global__ void split_x_kernel(const float* __restrict__ x) {
    size_t i = (size_t)blockIdx.x * blockDim.x + threadIdx.x;
    size_t total = (size_t)N_NODES * F_IN / 4;
    if (i >= total) return;
    float4 v = ((const float4*)x)[i];
    __nv_bfloat16 h0, h1, h2, h3, l0, l1, l2, l3;
    split_bf16(v.x, h0, l0); split_bf16(v.y, h1, l1);
    split_bf16(v.z, h2, l2); split_bf16(v.w, h3, l3);
    __nv_bfloat162 ph0 = __halves2bfloat162(h0, h1), ph1 = __halves2bfloat162(h2, h3);
    __nv_bfloat162 pl0 = __halves2bfloat162(l0, l1), pl1 = __halves2bfloat162(l2, l3);
    ((uint2*)g_xhi)[i] = make_uint2(*(uint32_t*)&ph0, *(uint32_t*)&ph1);
    ((uint2*)g_xlo)[i] = make_uint2(*(uint32_t*)&pl0, *(uint32_t*)&pl1);
}

__global__ void conv_weights_kernel(const float* __restrict__ W_in,
                                    const float* __restrict__ conv_W) {
    int i = blockIdx.x * blockDim.x + threadIdx.x;
    const int NIN = HID * F_IN;
    if (i < NIN) {
        int n = i / F_IN, k = i % F_IN;     // B[n][k] = W_in[k][n]
        __nv_bfloat16 hi, lo;
        split_bf16(W_in[(size_t)k * HID + n], hi, lo);
        g_Winhi[i] = hi; g_Winlo[i] = lo;
    } else {
        int j = i - NIN;
        if (j < NLAYERS * HID * HID) {
            int l = j / (HID * HID);
            int r = j % (HID * HID);
            int n = r / HID, k = r % HID;   // B[l][n][k] = conv_W[l][k][n]
            __nv_bfloat16 hi, lo;
            split_bf16(conv_W[(size_t)l * HID * HID + (size_t)k * HID + n], hi, lo);
            g_Wlhi[j] = hi; g_Wllo[j] = lo;
        }
    }
}

// ---------------- SpMM: mix = 0.9*(A@h) + 0.1*x0, + bf16 hi/lo split ----------------
__global__ void spmm_kernel() {
    const int lane = threadIdx.x & 31;
    const int wid = threadIdx.x >> 5;
    const int row = blockIdx.x * (blockDim.x >> 5) + wid;
    if (row >= N_NODES) return;

    const int start = g_rowptr[row];
    const int end = g_rowptr[row + 1];
    const float4* hp = (const float4*)g_h;

    float4 a = make_float4(0.f, 0.f, 0.f, 0.f);
    float4 b = make_float4(0.f, 0.f, 0.f, 0.f);

    int e = start;
    for (; e + 1 < end; e += 2) {
        int c0 = g_colv[e], c1 = g_colv[e + 1];
        float v0 = g_valv[e], v1 = g_valv[e + 1];
        float4 p0 = hp[(size_t)c0 * 64 + lane];
        float4 q0 = hp[(size_t)c0 * 64 + 32 + lane];
        float4 p1 = hp[(size_t)c1 * 64 + lane];
        float4 q1 = hp[(size_t)c1 * 64 + 32 + lane];
        a.x += v0 * p0.x; a.y += v0 * p0.y; a.z += v0 * p0.z; a.w += v0 * p0.w;
        b.x += v0 * q0.x; b.y += v0 * q0.y; b.z += v0 * q0.z; b.w += v0 * q0.w;
        a.x += v1 * p1.x; a.y += v1 * p1.y; a.z += v1 * p1.z; a.w += v1 * p1.w;
        b.x += v1 * q1.x; b.y += v1 * q1.y; b.z += v1 * q1.z; b.w += v1 * q1.w;
    }
    if (e < end) {
        int c0 = g_colv[e];
        float v0 = g_valv[e];
        float4 p0 = hp[(size_t)c0 * 64 + lane];
        float4 q0 = hp[(size_t)c0 * 64 + 32 + lane];
        a.x += v0 * p0.x; a.y += v0 * p0.y; a.z += v0 * p0.z; a.w += v0 * p0.w;
        b.x += v0 * q0.x; b.y += v0 * q0.y; b.z += v0 * q0.z; b.w += v0 * q0.w;
    }

    const float4* x04 = (const float4*)g_x0;
    float4 xa = x04[(size_t)row * 64 + lane];
    float4 xb = x04[(size_t)row * 64 + 32 + lane];
    float4 ma, mb;
    ma.x = (1.f - ALPHA) * a.x + ALPHA * xa.x;
    ma.y = (1.f - ALPHA) * a.y + ALPHA * xa.y;
    ma.z = (1.f - ALPHA) * a.z + ALPHA * xa.z;
    ma.w = (1.f - ALPHA) * a.w + ALPHA * xa.w;
    mb.x = (1.f - ALPHA) * b.x + ALPHA * xb.x;
    mb.y = (1.f - ALPHA) * b.y + ALPHA * xb.y;
    mb.z = (1.f - ALPHA) * b.z + ALPHA * xb.z;
    mb.w = (1.f - ALPHA) * b.w + ALPHA * xb.w;
    ((float4*)g_mix)[(size_t)row * 64 + lane] = ma;
    ((float4*)g_mix)[(size_t)row * 64 + 32 + lane] = mb;

    // bf16 hi/lo split; uint2 = 4 bf16 -> 64 uint2 per 256-wide row
    __nv_bfloat16 h0, h1, h2, h3, l0, l1, l2, l3;
    split_bf16(ma.x, h0, l0); split_bf16(ma.y, h1, l1);
    split_bf16(ma.z, h2, l2); split_bf16(ma.w, h3, l3);
    {
        __nv_bfloat162 p0 = __halves2bfloat162(h0, h1), p1 = __halves2bfloat162(h2, h3);
        __nv_bfloat162 q0 = __halves2bfloat162(l0, l1), q1 = __halves2bfloat162(l2, l3);
        ((uint2*)g_mhi)[(size_t)row * 64 + lane] = make_uint2(*(uint32_t*)&p0, *(uint32_t*)&p1);
        ((uint2*)g_mlo)[(size_t)row * 64 + lane] = make_uint2(*(uint32_t*)&q0, *(uint32_t*)&q1);
    }
    split_bf16(mb.x, h0, l0); split_bf16(mb.y, h1, l1);
    split_bf16(mb.z, h2, l2); split_bf16(mb.w, h3, l3);
    {
        __nv_bfloat162 p0 = __halves2bfloat162(h0, h1), p1 = __halves2bfloat162(h2, h3);
        __nv_bfloat162 q0 = __halves2bfloat162(l0, l1), q1 = __halves2bfloat162(l2, l3);
        ((uint2*)g_mhi)[(size_t)row * 64 + 32 + lane] = make_uint2(*(uint32_t*)&p0, *(uint32_t*)&p1);
        ((uint2*)g_mlo)[(size_t)row * 64 + 32 + lane] = make_uint2(*(uint32_t*)&q0, *(uint32_t*)&q1);
    }
}

// ---------------- bf16x3 MMA GEMM (mma.sync, sm_80+ path) ----------------
// C[M, 256] = relu(epilogue(A @ B^T)); A: [M,K] bf16 hi/lo; B: [256,K] bf16 hi/lo
// epilogue: mix != null -> (1-beta)*mix + beta*D ; else -> D + bias (writes out0 [+out1])
#define BM 128
#define BN 64
#define BKC 32
#define ASTRIDE 40                        // bf16 per smem row (80B, ldmatrix conflict-free)
#define A_STG (BM * ASTRIDE)              // 5120 bf16
#define B_STG (BN * ASTRIDE)              // 2560 bf16
#define STG_ELEMS (2 * A_STG + 2 * B_STG) // 15360 bf16 per stage
#define GEMM_SMEM (2 * STG_ELEMS * 2)     // 61440 bytes

__global__ void __launch_bounds__(256, 2)
mma_gemm_kernel(const __nv_bfloat16* __restrict__ Ahi, const __nv_bfloat16* __restrict__ Alo,
                int lda, int chunks,
                const __nv_bfloat16* __restrict__ Bhi, const __nv_bfloat16* __restrict__ Blo,
                const float* __restrict__ mix, const float* __restrict__ bias,
                float* __restrict__ out0, float* __restrict__ out1, float beta) {
    extern __shared__ __nv_bfloat16 sm[];
    const uint32_t smb = smem_u32(sm);
    const int tid = threadIdx.x;
    const int row0 = blockIdx.y * BM;
    const int n0 = blockIdx.x * BN;
    const int wid = tid >> 5, lane = tid & 31;
    const int wm = wid >> 1, wn = wid & 1;

    // ---- async stage loader ----
    auto load_chunk = [&](int c, int s) {
        const int base = s * STG_ELEMS;
        const __nv_bfloat16* ah = Ahi + (size_t)c * BKC;
        const __nv_bfloat16* al = Alo + (size_t)c * BKC;
#pragma unroll
        for (int i = 0; i < 2; i++) {
            int idx = tid + i * 256;        // 0..511 : 128 rows x 4 vec16
            int r = idx >> 2, v = idx & 3;
            int rg = row0 + r; if (rg >= N_NODES) rg = N_NODES - 1;
            uint32_t d = smb + (uint32_t)(base + r * ASTRIDE + v * 8) * 2;
            cp_async16(d, ah + (size_t)rg * lda + v * 8);
            cp_async16(d + A_STG * 2, al + (size_t)rg * lda + v * 8);
        }
        {
            int r = tid >> 2, v = tid & 3;  // 64 rows x 4 vec16
            uint32_t d = smb + (uint32_t)(base + 2 * A_STG + r * ASTRIDE + v * 8) * 2;
            size_t off = (size_t)(n0 + r) * lda + (size_t)c * BKC + v * 8;
            cp_async16(d, Bhi + off);
            cp_async16(d + B_STG * 2, Blo + off);
        }
    };

    float acc[2][4][4];
#pragma unroll
    for (int i = 0; i < 2; i++)
#pragma unroll
        for (int j = 0; j < 4; j++)
#pragma unroll
            for (int k = 0; k < 4; k++) acc[i][j][k] = 0.f;

    load_chunk(0, 0);
    CP_COMMIT();

    for (int c = 0; c < chunks; c++) {
        CP_WAIT0();
        __syncthreads();
        if (c + 1 < chunks) {
            load_chunk(c + 1, (c + 1) & 1);
            CP_COMMIT();
        }
        const int base = (c & 1) * STG_ELEMS;
        uint32_t aAddr = smb + (uint32_t)(base + (wm * 32 + (lane & 15)) * ASTRIDE + (lane >> 4) * 8) * 2;
        uint32_t bAddr = smb + (uint32_t)(base + 2 * A_STG + (wn * 32 + (lane & 7)) * ASTRIDE + ((lane >> 3) & 1) * 8) * 2;
#pragma unroll
        for (int ks = 0; ks < 2; ks++) {
            uint32_t ah[2][4], al[2][4], bh[4][2], bl[4][2];
#pragma unroll
            for (int mt = 0; mt < 2; mt++) {
                uint32_t addr = aAddr + (uint32_t)mt * (16 * ASTRIDE * 2) + ks * 32;
                ldmx4(ah[mt], addr);
                ldmx4(al[mt], addr + A_STG * 2);
            }
#pragma unroll
            for (int nt = 0; nt < 4; nt++) {
                uint32_t addr = bAddr + (uint32_t)nt * (8 * ASTRIDE * 2) + ks * 32;
                ldmx2(bh[nt], addr);
                ldmx2(bl[nt], addr + B_STG * 2);
            }
#pragma unroll
            for (int mt = 0; mt < 2; mt++)
#pragma unroll
                for (int nt = 0; nt < 4; nt++) {
                    mma16816(acc[mt][nt], ah[mt], bh[nt]);
                    mma16816(acc[mt][nt], ah[mt], bl[nt]);
                    mma16816(acc[mt][nt], al[mt], bh[nt]);
                }
        }
        __syncthreads();
    }

    // ---- epilogue ----
    const int r_base = row0 + wm * 32 + (lane >> 2);
    const int c_base = n0 + wn * 32 + (lane & 3) * 2;
    if (mix) {
        const float wmix = 1.f - beta;
#pragma unroll
        for (int mt = 0; mt < 2; mt++)
#pragma unroll
            for (int half = 0; half < 2; half++) {
                int r = r_base + mt * 16 + half * 8;
                if (r >= N_NODES) continue;
#pragma unroll
                for (int nt = 0; nt < 4; nt++) {
                    int cc = c_base + nt * 8;
                    float2 mv = *(const float2*)&mix[(size_t)r * HID + cc];
                    float v0 = fmaxf(wmix * mv.x + beta * acc[mt][nt][half * 2 + 0], 0.f);
                    float v1 = fmaxf(wmix * mv.y + beta * acc[mt][nt][half * 2 + 1], 0.f);
                    *(float2*)&out0[(size_t)r * HID + cc] = make_float2(v0, v1);
                }
            }
    } else {
#pragma unroll
        for (int mt = 0; mt < 2; mt++)
#pragma unroll
            for (int half = 0; half < 2; half++) {
                int r = r_base + mt * 16 + half * 8;
                if (r >= N_NODES) continue;
#pragma unroll
                for (int nt = 0; nt < 4; nt++) {
                    int cc = c_base + nt * 8;
                    float v0 = fmaxf(acc[mt][nt][half * 2 + 0] + bias[cc], 0.f);
                    float v1 = fmaxf(acc[mt][nt][half * 2 + 1] + bias[cc + 1], 0.f);
                    *(float2*)&out0[(size_t)r * HID + cc] = make_float2(v0, v1);
                    if (out1) *(float2*)&out1[(size_t)r * HID + cc] = make_float2(v0, v1);
                }
            }
    }
}

// ---------------- SIMT GEMM for output layer (fp32) ----------------
template <int TBM, int TBN, int TBK, int TTM, int TTN>
__global__ __launch_bounds__((TBM / TTM) * (TBN / TTN))
void gemm_kernel(const float* __restrict__ A, const float* __restrict__ B,
                 float* __restrict__ C, int M, int N, int K,
                 const float* __restrict__ bias) {
    __shared__ float As[TBK][TBM + 4];
    __shared__ float Bs[TBK][TBN];
    constexpr int THREADS = (TBM / TTM) * (TBN / TTN);
    const int tid = threadIdx.x;
    const int blockRow = blockIdx.y;
    const int blockCol = blockIdx.x;
    const int tcol = tid % (TBN / TTN);
    const int trow = tid / (TBN / TTN);

    float acc[TTM][TTN];
#pragma unroll
    for (int i = 0; i < TTM; i++)
#pragma unroll
        for (int j = 0; j < TTN; j++) acc[i][j] = 0.f;

    constexpr int A_VEC_PER_ROW = TBK / 4;
    const int aRow0 = tid / A_VEC_PER_ROW;
    const int aCol = (tid % A_VEC_PER_ROW) * 4;
    constexpr int A_ROW_STRIDE = THREADS / A_VEC_PER_ROW;
    constexpr int B_VEC_PER_ROW = TBN / 4;
    const int bRow0 = tid / B_VEC_PER_ROW;
    const int bCol = (tid % B_VEC_PER_ROW) * 4;
    constexpr int B_ROW_STRIDE = THREADS / B_VEC_PER_ROW;

    const float* Abase = A + (size_t)blockRow * TBM * K;
    const float* Bbase = B + (size_t)blockCol * TBN;

    for (int k0 = 0; k0 < K; k0 += TBK) {
#pragma unroll
        for (int r = 0; r < TBM / A_ROW_STRIDE; r++) {
            int rr = aRow0 + r * A_ROW_STRIDE;
            int gRow = blockRow * TBM + rr;
            float4 v = make_float4(0.f, 0.f, 0.f, 0.f);
            if (gRow < M) v = *(const float4*)(Abase + (size_t)rr * K + k0 + aCol);
            As[aCol + 0][rr] = v.x; As[aCol + 1][rr] = v.y;
            As[aCol + 2][rr] = v.z; As[aCol + 3][rr] = v.w;
        }
#pragma unroll
        for (int r = 0; r < TBK / B_ROW_STRIDE; r++) {
            int rr = bRow0 + r * B_ROW_STRIDE;
            *(float4*)&Bs[rr][bCol] = *(const float4*)(Bbase + (size_t)(k0 + rr) * N + bCol);
        }
        __syncthreads();
#pragma unroll
        for (int k = 0; k < TBK; k++) {
            float a[TTM], b[TTN];
#pragma unroll
            for (int i = 0; i < TTM; i++) a[i] = As[k][trow * TTM + i];
#pragma unroll
            for (int j = 0; j < TTN; j++) b[j] = Bs[k][tcol * TTN + j];
#pragma unroll
            for (int i = 0; i < TTM; i++)
#pragma unroll
                for (int j = 0; j < TTN; j++) acc[i][j] += a[i] * b[j];
        }
        __syncthreads();
    }
#pragma unroll
    for (int i = 0; i < TTM; i++) {
        int gr = blockRow * TBM + trow * TTM + i;
        if (gr >= M) continue;
#pragma unroll
        for (int j = 0; j < TTN; j++) {
            int gc = blockCol * TBN + tcol * TTN + j;
            C[(size_t)gr * N + gc] = acc[i][j] + bias[gc];
        }
    }
}

// ---------------- log_softmax ----------------
__global__ void logsoftmax_kernel(float* __restrict__ logits) {
    const int lane = threadIdx.x & 31;
    const int wid = threadIdx.x >> 5;
    const int row = blockIdx.x * (blockDim.x >> 5) + wid;
    if (row >= N_NODES) return;
    float* p = logits + (size_t)row * NCLS;
    float v0 = p[lane];
    float v1 = p[lane + 32];
    float m = fmaxf(v0, v1);
#pragma unroll
    for (int off = 16; off > 0; off >>= 1)
        m = fmaxf(m, __shfl_xor_sync(0xffffffffu, m, off));
    float s = expf(v0 - m) + expf(v1 - m);
#pragma unroll
    for (int off = 16; off > 0; off >>= 1)
        s += __shfl_xor_sync(0xffffffffu, s, off);
    float lse = m + logf(s);
    p[lane] = v0 - lse;
    p[lane + 32] = v1 - lse;
}

// ---------------- launch ----------------
extern "C" void kernel_launch(void* const* d_in, const int* in_sizes, int n_in,
                              void* d_out, int out_size) {
    const float* x        = (const float*)d_in[0];
    const float* edge_val = (const float*)d_in[1];
    const float* W_in     = (const float*)d_in[2];
    const float* b_in     = (const float*)d_in[3];
    const float* conv_W   = (const float*)d_in[4];
    const float* W_out    = (const float*)d_in[5];
    const float* b_out    = (const float*)d_in[6];
    const int*   edge_row = (const int*)d_in[7];
    const int*   edge_col = (const int*)d_in[8];
    float* out = (float*)d_out;

    float *h_ptr, *x0_ptr, *mix_ptr;
    __nv_bfloat16 *xhi, *xlo, *mhi, *mlo, *winh, *winl, *wlh, *wll;
    cudaGetSymbolAddress((void**)&h_ptr, g_h);
    cudaGetSymbolAddress((void**)&x0_ptr, g_x0);
    cudaGetSymbolAddress((void**)&mix_ptr, g_mix);
    cudaGetSymbolAddress((void**)&xhi, g_xhi);
    cudaGetSymbolAddress((void**)&xlo, g_xlo);
    cudaGetSymbolAddress((void**)&mhi, g_mhi);
    cudaGetSymbolAddress((void**)&mlo, g_mlo);
    cudaGetSymbolAddress((void**)&winh, g_Winhi);
    cudaGetSymbolAddress((void**)&winl, g_Winlo);
    cudaGetSymbolAddress((void**)&wlh, g_Wlhi);
    cudaGetSymbolAddress((void**)&wll, g_Wllo);

    cudaFuncSetAttribute(mma_gemm_kernel, cudaFuncAttributeMaxDynamicSharedMemorySize, GEMM_SMEM);

    // 1. CSR build + precision splits
    zero_cnt_kernel<<<(N_NODES + 255) / 256, 256>>>();
    count_kernel<<<(N_EDGES + 255) / 256, 256>>>(edge_row);
    scan_kernel<<<1, 1024>>>();
    scatter_kernel<<<(N_EDGES + 255) / 256, 256>>>(edge_row, edge_col, edge_val);
    split_x_kernel<<<(int)(((size_t)N_NODES * F_IN / 4 + 255) / 256), 256>>>(x);
    conv_weights_kernel<<<(HID * F_IN + NLAYERS * HID * HID + 255) / 256, 256>>>(W_in, conv_W);

    const dim3 ggrid(HID / BN, (N_NODES + BM - 1) / BM);

    // 2. input GEMM: h = x0 = relu(x @ W_in + b_in)
    mma_gemm_kernel<<<ggrid, 256, GEMM_SMEM>>>(
        xhi, xlo, F_IN, F_IN / BKC, winh, winl, nullptr, b_in, h_ptr, x0_ptr, 0.f);

    // 3. GCN2 layers
    for (int l = 0; l < NLAYERS; l++) {
        float beta = (float)log(0.5 / (double)(l + 1) + 1.0);
        spmm_kernel<<<(N_NODES + 7) / 8, 256>>>();
        mma_gemm_kernel<<<ggrid, 256, GEMM_SMEM>>>(
            mhi, mlo, HID, HID / BKC,
            wlh + (size_t)l * HID * HID, wll + (size_t)l * HID * HID,
            mix_ptr, nullptr, h_ptr, nullptr, beta);
    }

    // 4. output GEMM + log_softmax
    {
        dim3 grid(NCLS / 64, (N_NODES + 127) / 128);
        gemm_kernel<128, 64, 16, 8, 4><<<grid, 256>>>(h_ptr, W_out, out, N_NODES, NCLS, HID, b_out);
    }
    logsoftmax_kernel<<<(N_NODES + 7) / 8, 256>>>(out);
}

// round 6
// speedup vs baseline: 1.7559x; 1.1175x over previous
#include <cuda_runtime.h>
#include <cuda_bf16.h>
#include <math.h>
#include <stdint.h>

#define N_NODES 100000
#define N_EDGES 3200000
#define F_IN    512
#define HID     256
#define NCLS    64
#define NLAYERS 8
#define ALPHA   0.1f

// ---------------- device scratch (static, no allocations) ----------------
__device__ float g_hA[(size_t)N_NODES * HID];            // h ping
__device__ float g_hB[(size_t)N_NODES * HID];            // h pong
__device__ float g_x0[(size_t)N_NODES * HID];
__device__ __nv_bfloat16 g_mhi[(size_t)N_NODES * HID];   // last-layer h hi
__device__ __nv_bfloat16 g_mlo[(size_t)N_NODES * HID];   // last-layer h lo
__device__ __nv_bfloat16 g_xhi[(size_t)N_NODES * F_IN];
__device__ __nv_bfloat16 g_xlo[(size_t)N_NODES * F_IN];
__device__ __nv_bfloat16 g_Winhi[HID * F_IN];            // [n][k]
__device__ __nv_bfloat16 g_Winlo[HID * F_IN];
__device__ __nv_bfloat16 g_Wlhi[NLAYERS * HID * HID];    // [l][n][k]
__device__ __nv_bfloat16 g_Wllo[NLAYERS * HID * HID];
__device__ __nv_bfloat16 g_Wouthi[NCLS * HID];           // [n][k]
__device__ __nv_bfloat16 g_Woutlo[NCLS * HID];
__device__ int   g_rowptr[N_NODES + 1];
__device__ int   g_cnt[N_NODES];
__device__ int   g_colv[N_EDGES];
__device__ float g_valv[N_EDGES];

// ---------------- PTX helpers (arch-agnostic: sm_80+) ----------------
__device__ __forceinline__ uint32_t smem_u32(const void* p) {
    uint32_t a;
    asm("{ .reg .u64 t; cvta.to.shared.u64 t, %1; cvt.u32.u64 %0, t; }" : "=r"(a) : "l"(p));
    return a;
}
__device__ __forceinline__ void cp_async16(uint32_t dst, const void* src) {
    asm volatile("cp.async.cg.shared.global [%0], [%1], 16;" :: "r"(dst), "l"(src));
}
#define CP_COMMIT() asm volatile("cp.async.commit_group;" ::: "memory")
#define CP_WAIT0()  asm volatile("cp.async.wait_group 0;" ::: "memory")

__device__ __forceinline__ void ldmx4(uint32_t* r, uint32_t addr) {
    asm volatile("ldmatrix.sync.aligned.m8n8.x4.shared.b16 {%0,%1,%2,%3}, [%4];"
                 : "=r"(r[0]), "=r"(r[1]), "=r"(r[2]), "=r"(r[3]) : "r"(addr));
}
__device__ __forceinline__ void ldmx2(uint32_t* r, uint32_t addr) {
    asm volatile("ldmatrix.sync.aligned.m8n8.x2.shared.b16 {%0,%1}, [%2];"
                 : "=r"(r[0]), "=r"(r[1]) : "r"(addr));
}
__device__ __forceinline__ void mma16816(float* d, const uint32_t* a, const uint32_t* b) {
    asm volatile("mma.sync.aligned.m16n8k16.row.col.f32.bf16.bf16.f32 "
                 "{%0,%1,%2,%3}, {%4,%5,%6,%7}, {%8,%9}, {%0,%1,%2,%3};"
                 : "+f"(d[0]), "+f"(d[1]), "+f"(d[2]), "+f"(d[3])
                 : "r"(a[0]), "r"(a[1]), "r"(a[2]), "r"(a[3]), "r"(b[0]), "r"(b[1]));
}

// ---------------- CSR build ----------------
__global__ void zero_cnt_kernel() {
    int i = blockIdx.x * blockDim.x + threadIdx.x;
    if (i < N_NODES) g_cnt[i] = 0;
}
__global__ void count_kernel(const int* __restrict__ edge_row) {
    int e = blockIdx.x * blockDim.x + threadIdx.x;
    if (e < N_EDGES) atomicAdd(&g_cnt[edge_row[e]], 1);
}
__global__ void scan_kernel() {
    __shared__ int s[1024];
    const int t = threadIdx.x;
    const int CH = (N_NODES + 1023) / 1024;
    int begin = t * CH;
    int end = begin + CH; if (end > N_NODES) end = N_NODES;
    if (begin > N_NODES) begin = N_NODES;
    int sum = 0;
    for (int i = begin; i < end; i++) sum += g_cnt[i];
    s[t] = sum;
    __syncthreads();
    for (int off = 1; off < 1024; off <<= 1) {
        int v = (t >= off) ? s[t - off] : 0;
        __syncthreads();
        s[t] += v;
        __syncthreads();
    }
    int run = s[t] - sum;
    for (int i = begin; i < end; i++) {
        int c = g_cnt[i];
        g_rowptr[i] = run;
        run += c;
        g_cnt[i] = 0;
    }
    if (t == 1023) g_rowptr[N_NODES] = s[1023];
}
__global__ void scatter_kernel(const int* __restrict__ edge_row,
                               const int* __restrict__ edge_col,
                               const float* __restrict__ edge_val) {
    int e = blockIdx.x * blockDim.x + threadIdx.x;
    if (e < N_EDGES) {
        int r = edge_row[e];
        int pos = g_rowptr[r] + atomicAdd(&g_cnt[r], 1);
        g_colv[pos] = edge_col[e];
        g_valv[pos] = edge_val[e];
    }
}

// ---------------- conversions ----------------
__device__ __forceinline__ void split_bf16(float v, __nv_bfloat16& hi, __nv_bfloat16& lo) {
    hi = __float2bfloat16_rn(v);
    lo = __float2bfloat16_rn(v - __bfloat162float(hi));
}

__global__ void split_x_kernel(const float* __restrict__ x) {
    size_t i = (size_t)blockIdx.x * blockDim.x + threadIdx.x;
    size_t total = (size_t)N_NODES * F_IN / 4;
    if (i >= total) return;
    float4 v = ((const float4*)x)[i];
    __nv_bfloat16 h0, h1, h2, h3, l0, l1, l2, l3;
    split_bf16(v.x, h0, l0); split_bf16(v.y, h1, l1);
    split_bf16(v.z, h2, l2); split_bf16(v.w, h3, l3);
    __nv_bfloat162 ph0 = __halves2bfloat162(h0, h1), ph1 = __halves2bfloat162(h2, h3);
    __nv_bfloat162 pl0 = __halves2bfloat162(l0, l1), pl1 = __halves2bfloat162(l2, l3);
    ((uint2*)g_xhi)[i] = make_uint2(*(uint32_t*)&ph0, *(uint32_t*)&ph1);
    ((uint2*)g_xlo)[i] = make_uint2(*(uint32_t*)&pl0, *(uint32_t*)&pl1);
}

__global__ void conv_weights_kernel(const float* __restrict__ W_in,
                                    const float* __restrict__ conv_W,
                                    const float* __restrict__ W_out) {
    int i = blockIdx.x * blockDim.x + threadIdx.x;
    const int NIN = HID * F_IN;
    const int NL = NLAYERS * HID * HID;
    if (i < NIN) {
        int n = i / F_IN, k = i % F_IN;     // B[n][k] = W_in[k][n]
        __nv_bfloat16 hi, lo;
        split_bf16(W_in[(size_t)k * HID + n], hi, lo);
        g_Winhi[i] = hi; g_Winlo[i] = lo;
    } else if (i < NIN + NL) {
        int j = i - NIN;
        int l = j / (HID * HID);
        int r = j % (HID * HID);
        int n = r / HID, k = r % HID;       // B[l][n][k] = conv_W[l][k][n]
        __nv_bfloat16 hi, lo;
        split_bf16(conv_W[(size_t)l * HID * HID + (size_t)k * HID + n], hi, lo);
        g_Wlhi[j] = hi; g_Wllo[j] = lo;
    } else {
        int j = i - NIN - NL;
        if (j < NCLS * HID) {
            int n = j / HID, k = j % HID;   // B[n][k] = W_out[k][n]
            __nv_bfloat16 hi, lo;
            split_bf16(W_out[(size_t)k * NCLS + n], hi, lo);
            g_Wouthi[j] = hi; g_Woutlo[j] = lo;
        }
    }
}

// ============ fused layer: SpMM + mix + bf16 split (SMEM) + MMA GEMM ============
// Reads h_in (ping), writes h_out (pong) -- disjoint buffers, no cross-CTA race.
#define FBM 64
#define AST 264                         // bf16 per A smem row (528B, conflict-free)
#define A_ELEMS (FBM * AST)             // 16896 bf16 per matrix
#define WSTRIDE 40
#define W_ELEMS (64 * WSTRIDE)          // 2560 bf16 per matrix per stage
#define W_BASE (2 * A_ELEMS)            // 33792
#define FUSED_SMEM ((W_BASE + 2 * 2 * W_ELEMS) * 2)   // 88064 bytes

__global__ void __launch_bounds__(512, 2)
fused_layer_kernel(const float* __restrict__ h_in, float* __restrict__ h_out,
                   const __nv_bfloat16* __restrict__ Whi,
                   const __nv_bfloat16* __restrict__ Wlo,
                   float beta, int last) {
    extern __shared__ __nv_bfloat16 sm[];
    const uint32_t smb = smem_u32(sm);
    const int tid = threadIdx.x;
    const int wid = tid >> 5, lane = tid & 31;
    const int row0 = blockIdx.x * FBM;

    __nv_bfloat16* Ahi_s = sm;
    __nv_bfloat16* Alo_s = sm + A_ELEMS;

    // ---------------- phase 1: SpMM + mix + split into SMEM ----------------
    const float4* hp = (const float4*)h_in;
#pragma unroll
    for (int it = 0; it < FBM / 16; it++) {
        const int rl = it * 16 + wid;
        const int row = row0 + rl;
        float4 a = make_float4(0.f, 0.f, 0.f, 0.f);
        float4 b = make_float4(0.f, 0.f, 0.f, 0.f);
        float4 ma = a, mb = b;
        if (row < N_NODES) {
            const int start = g_rowptr[row];
            const int end = g_rowptr[row + 1];
            int e = start;
            for (; e + 3 < end; e += 4) {
                int c0 = g_colv[e], c1 = g_colv[e + 1], c2 = g_colv[e + 2], c3 = g_colv[e + 3];
                float v0 = g_valv[e], v1 = g_valv[e + 1], v2 = g_valv[e + 2], v3 = g_valv[e + 3];
                float4 p0 = hp[(size_t)c0 * 64 + lane];
                float4 q0 = hp[(size_t)c0 * 64 + 32 + lane];
                float4 p1 = hp[(size_t)c1 * 64 + lane];
                float4 q1 = hp[(size_t)c1 * 64 + 32 + lane];
                float4 p2 = hp[(size_t)c2 * 64 + lane];
                float4 q2 = hp[(size_t)c2 * 64 + 32 + lane];
                float4 p3 = hp[(size_t)c3 * 64 + lane];
                float4 q3 = hp[(size_t)c3 * 64 + 32 + lane];
                a.x += v0 * p0.x; a.y += v0 * p0.y; a.z += v0 * p0.z; a.w += v0 * p0.w;
                b.x += v0 * q0.x; b.y += v0 * q0.y; b.z += v0 * q0.z; b.w += v0 * q0.w;
                a.x += v1 * p1.x; a.y += v1 * p1.y; a.z += v1 * p1.z; a.w += v1 * p1.w;
                b.x += v1 * q1.x; b.y += v1 * q1.y; b.z += v1 * q1.z; b.w += v1 * q1.w;
                a.x += v2 * p2.x; a.y += v2 * p2.y; a.z += v2 * p2.z; a.w += v2 * p2.w;
                b.x += v2 * q2.x; b.y += v2 * q2.y; b.z += v2 * q2.z; b.w += v2 * q2.w;
                a.x += v3 * p3.x; a.y += v3 * p3.y; a.z += v3 * p3.z; a.w += v3 * p3.w;
                b.x += v3 * q3.x; b.y += v3 * q3.y; b.z += v3 * q3.z; b.w += v3 * q3.w;
            }
            for (; e < end; e++) {
                int c0 = g_colv[e];
                float v0 = g_valv[e];
                float4 p0 = hp[(size_t)c0 * 64 + lane];
                float4 q0 = hp[(size_t)c0 * 64 + 32 + lane];
                a.x += v0 * p0.x; a.y += v0 * p0.y; a.z += v0 * p0.z; a.w += v0 * p0.w;
                b.x += v0 * q0.x; b.y += v0 * q0.y; b.z += v0 * q0.z; b.w += v0 * q0.w;
            }
            float4 xa = ((const float4*)g_x0)[(size_t)row * 64 + lane];
            float4 xb = ((const float4*)g_x0)[(size_t)row * 64 + 32 + lane];
            ma.x = (1.f - ALPHA) * a.x + ALPHA * xa.x;
            ma.y = (1.f - ALPHA) * a.y + ALPHA * xa.y;
            ma.z = (1.f - ALPHA) * a.z + ALPHA * xa.z;
            ma.w = (1.f - ALPHA) * a.w + ALPHA * xa.w;
            mb.x = (1.f - ALPHA) * b.x + ALPHA * xb.x;
            mb.y = (1.f - ALPHA) * b.y + ALPHA * xb.y;
            mb.z = (1.f - ALPHA) * b.z + ALPHA * xb.z;
            mb.w = (1.f - ALPHA) * b.w + ALPHA * xb.w;
        }
        __nv_bfloat16 h0, h1, h2, h3, l0, l1, l2, l3;
        split_bf16(ma.x, h0, l0); split_bf16(ma.y, h1, l1);
        split_bf16(ma.z, h2, l2); split_bf16(ma.w, h3, l3);
        {
            __nv_bfloat162 p0 = __halves2bfloat162(h0, h1), p1 = __halves2bfloat162(h2, h3);
            __nv_bfloat162 q0 = __halves2bfloat162(l0, l1), q1 = __halves2bfloat162(l2, l3);
            *(uint2*)(Ahi_s + rl * AST + lane * 4) = make_uint2(*(uint32_t*)&p0, *(uint32_t*)&p1);
            *(uint2*)(Alo_s + rl * AST + lane * 4) = make_uint2(*(uint32_t*)&q0, *(uint32_t*)&q1);
        }
        split_bf16(mb.x, h0, l0); split_bf16(mb.y, h1, l1);
        split_bf16(mb.z, h2, l2); split_bf16(mb.w, h3, l3);
        {
            __nv_bfloat162 p0 = __halves2bfloat162(h0, h1), p1 = __halves2bfloat162(h2, h3);
            __nv_bfloat162 q0 = __halves2bfloat162(l0, l1), q1 = __halves2bfloat162(l2, l3);
            *(uint2*)(Ahi_s + rl * AST + 128 + lane * 4) = make_uint2(*(uint32_t*)&p0, *(uint32_t*)&p1);
            *(uint2*)(Alo_s + rl * AST + 128 + lane * 4) = make_uint2(*(uint32_t*)&q0, *(uint32_t*)&q1);
        }
    }
    __syncthreads();

    // ---------------- phase 2: GEMM mix @ W^T + epilogue ----------------
    const int wm = wid >> 2;        // 0..3 : 16-row tile
    const int wn = wid & 3;         // 0..3 : 16-col tile within 64
    const float wmix = 1.f - beta;

    auto load_w = [&](int nt4, int c, int s) {
        int idx = tid & 255;
        int r = idx >> 2, v = idx & 3;
        const __nv_bfloat16* src = (tid < 256 ? Whi : Wlo)
                                 + (size_t)(nt4 * 64 + r) * HID + c * 32 + v * 8;
        uint32_t off = W_BASE + s * (2 * W_ELEMS) + (tid < 256 ? 0 : W_ELEMS)
                     + r * WSTRIDE + v * 8;
        cp_async16(smb + off * 2, src);
    };

    for (int nt4 = 0; nt4 < 4; nt4++) {
        float acc[2][4];
#pragma unroll
        for (int i = 0; i < 2; i++)
#pragma unroll
            for (int j = 0; j < 4; j++) acc[i][j] = 0.f;

        load_w(nt4, 0, 0);
        CP_COMMIT();
        for (int c = 0; c < 8; c++) {
            CP_WAIT0();
            __syncthreads();
            if (c + 1 < 8) { load_w(nt4, c + 1, (c + 1) & 1); CP_COMMIT(); }
            const uint32_t wsb = smb + (W_BASE + (c & 1) * (2 * W_ELEMS)) * 2;
#pragma unroll
            for (int ks = 0; ks < 2; ks++) {
                uint32_t ah[4], al[4], bh[2][2], bl[2][2];
                uint32_t aAddr = smb + (uint32_t)((wm * 16 + (lane & 15)) * AST
                                + c * 32 + ks * 16 + (lane >> 4) * 8) * 2;
                ldmx4(ah, aAddr);
                ldmx4(al, aAddr + A_ELEMS * 2);
#pragma unroll
                for (int nt = 0; nt < 2; nt++) {
                    uint32_t bAddr = wsb + (uint32_t)((wn * 16 + nt * 8 + (lane & 7)) * WSTRIDE
                                    + ks * 16 + ((lane >> 3) & 1) * 8) * 2;
                    ldmx2(bh[nt], bAddr);
                    ldmx2(bl[nt], bAddr + W_ELEMS * 2);
                }
#pragma unroll
                for (int nt = 0; nt < 2; nt++) {
                    mma16816(acc[nt], ah, bh[nt]);
                    mma16816(acc[nt], ah, bl[nt]);
                    mma16816(acc[nt], al, bh[nt]);
                }
            }
            __syncthreads();
        }

        // epilogue for this 64-col tile
        const int r_loc0 = wm * 16 + (lane >> 2);
#pragma unroll
        for (int half = 0; half < 2; half++) {
            int rl = r_loc0 + half * 8;
            int grow = row0 + rl;
            if (grow >= N_NODES) continue;
#pragma unroll
            for (int nt = 0; nt < 2; nt++) {
                int gc = nt4 * 64 + wn * 16 + nt * 8 + (lane & 3) * 2;
                uint32_t hiw = *(uint32_t*)(Ahi_s + rl * AST + gc);
                uint32_t low = *(uint32_t*)(Alo_s + rl * AST + gc);
                __nv_bfloat162 hv = *(__nv_bfloat162*)&hiw;
                __nv_bfloat162 lv = *(__nv_bfloat162*)&low;
                float m0 = __bfloat162float(hv.x) + __bfloat162float(lv.x);
                float m1 = __bfloat162float(hv.y) + __bfloat162float(lv.y);
                float v0 = fmaxf(wmix * m0 + beta * acc[nt][half * 2 + 0], 0.f);
                float v1 = fmaxf(wmix * m1 + beta * acc[nt][half * 2 + 1], 0.f);
                if (!last) {
                    *(float2*)&h_out[(size_t)grow * HID + gc] = make_float2(v0, v1);
                } else {
                    __nv_bfloat16 hh0, hl0, hh1, hl1;
                    split_bf16(v0, hh0, hl0);
                    split_bf16(v1, hh1, hl1);
                    __nv_bfloat162 ph = __halves2bfloat162(hh0, hh1);
                    __nv_bfloat162 pl = __halves2bfloat162(hl0, hl1);
                    *(uint32_t*)&g_mhi[(size_t)grow * HID + gc] = *(uint32_t*)&ph;
                    *(uint32_t*)&g_mlo[(size_t)grow * HID + gc] = *(uint32_t*)&pl;
                }
            }
        }
        __syncthreads();
    }
}

// ---------------- bf16x3 MMA GEMM (input + output layers) ----------------
#define BM 128
#define BN 64
#define BKC 32
#define ASTRIDE 40
#define A_STG (BM * ASTRIDE)
#define B_STG (BN * ASTRIDE)
#define STG_ELEMS (2 * A_STG + 2 * B_STG)
#define GEMM_SMEM (2 * STG_ELEMS * 2)

__global__ void __launch_bounds__(256, 2)
mma_gemm_kernel(const __nv_bfloat16* __restrict__ Ahi, const __nv_bfloat16* __restrict__ Alo,
                int lda, int chunks,
                const __nv_bfloat16* __restrict__ Bhi, const __nv_bfloat16* __restrict__ Blo,
                const float* __restrict__ bias,
                float* __restrict__ out0, float* __restrict__ out1,
                int ldc, int do_relu) {
    extern __shared__ __nv_bfloat16 smg[];
    const uint32_t smb = smem_u32(smg);
    const int tid = threadIdx.x;
    const int row0 = blockIdx.y * BM;
    const int n0 = blockIdx.x * BN;
    const int wid = tid >> 5, lane = tid & 31;
    const int wm = wid >> 1, wn = wid & 1;

    auto load_chunk = [&](int c, int s) {
        const int base = s * STG_ELEMS;
        const __nv_bfloat16* ah = Ahi + (size_t)c * BKC;
        const __nv_bfloat16* al = Alo + (size_t)c * BKC;
#pragma unroll
        for (int i = 0; i < 2; i++) {
            int idx = tid + i * 256;
            int r = idx >> 2, v = idx & 3;
            int rg = row0 + r; if (rg >= N_NODES) rg = N_NODES - 1;
            uint32_t d = smb + (uint32_t)(base + r * ASTRIDE + v * 8) * 2;
            cp_async16(d, ah + (size_t)rg * lda + v * 8);
            cp_async16(d + A_STG * 2, al + (size_t)rg * lda + v * 8);
        }
        {
            int r = tid >> 2, v = tid & 3;
            uint32_t d = smb + (uint32_t)(base + 2 * A_STG + r * ASTRIDE + v * 8) * 2;
            size_t off = (size_t)(n0 + r) * lda + (size_t)c * BKC + v * 8;
            cp_async16(d, Bhi + off);
            cp_async16(d + B_STG * 2, Blo + off);
        }
    };

    float acc[2][4][4];
#pragma unroll
    for (int i = 0; i < 2; i++)
#pragma unroll
        for (int j = 0; j < 4; j++)
#pragma unroll
            for (int k = 0; k < 4; k++) acc[i][j][k] = 0.f;

    load_chunk(0, 0);
    CP_COMMIT();

    for (int c = 0; c < chunks; c++) {
        CP_WAIT0();
        __syncthreads();
        if (c + 1 < chunks) {
            load_chunk(c + 1, (c + 1) & 1);
            CP_COMMIT();
        }
        const int base = (c & 1) * STG_ELEMS;
        uint32_t aAddr = smb + (uint32_t)(base + (wm * 32 + (lane & 15)) * ASTRIDE + (lane >> 4) * 8) * 2;
        uint32_t bAddr = smb + (uint32_t)(base + 2 * A_STG + (wn * 32 + (lane & 7)) * ASTRIDE + ((lane >> 3) & 1) * 8) * 2;
#pragma unroll
        for (int ks = 0; ks < 2; ks++) {
            uint32_t ah[2][4], al[2][4], bh[4][2], bl[4][2];
#pragma unroll
            for (int mt = 0; mt < 2; mt++) {
                uint32_t addr = aAddr + (uint32_t)mt * (16 * ASTRIDE * 2) + ks * 32;
                ldmx4(ah[mt], addr);
                ldmx4(al[mt], addr + A_STG * 2);
            }
#pragma unroll
            for (int nt = 0; nt < 4; nt++) {
                uint32_t addr = bAddr + (uint32_t)nt * (8 * ASTRIDE * 2) + ks * 32;
                ldmx2(bh[nt], addr);
                ldmx2(bl[nt], addr + B_STG * 2);
            }
#pragma unroll
            for (int mt = 0; mt < 2; mt++)
#pragma unroll
                for (int nt = 0; nt < 4; nt++) {
                    mma16816(acc[mt][nt], ah[mt], bh[nt]);
                    mma16816(acc[mt][nt], ah[mt], bl[nt]);
                    mma16816(acc[mt][nt], al[mt], bh[nt]);
                }
        }
        __syncthreads();
    }

    const int r_base = row0 + wm * 32 + (lane >> 2);
    const int c_base = n0 + wn * 32 + (lane & 3) * 2;
#pragma unroll
    for (int mt = 0; mt < 2; mt++)
#pragma unroll
        for (int half = 0; half < 2; half++) {
            int r = r_base + mt * 16 + half * 8;
            if (r >= N_NODES) continue;
#pragma unroll
            for (int nt = 0; nt < 4; nt++) {
                int cc = c_base + nt * 8;
                float v0 = acc[mt][nt][half * 2 + 0] + bias[cc];
                float v1 = acc[mt][nt][half * 2 + 1] + bias[cc + 1];
                if (do_relu) { v0 = fmaxf(v0, 0.f); v1 = fmaxf(v1, 0.f); }
                *(float2*)&out0[(size_t)r * ldc + cc] = make_float2(v0, v1);
                if (out1) *(float2*)&out1[(size_t)r * ldc + cc] = make_float2(v0, v1);
            }
        }
}

// ---------------- log_softmax ----------------
__global__ void logsoftmax_kernel(float* __restrict__ logits) {
    const int lane = threadIdx.x & 31;
    const int wid = threadIdx.x >> 5;
    const int row = blockIdx.x * (blockDim.x >> 5) + wid;
    if (row >= N_NODES) return;
    float* p = logits + (size_t)row * NCLS;
    float v0 = p[lane];
    float v1 = p[lane + 32];
    float m = fmaxf(v0, v1);
#pragma unroll
    for (int off = 16; off > 0; off >>= 1)
        m = fmaxf(m, __shfl_xor_sync(0xffffffffu, m, off));
    float s = expf(v0 - m) + expf(v1 - m);
#pragma unroll
    for (int off = 16; off > 0; off >>= 1)
        s += __shfl_xor_sync(0xffffffffu, s, off);
    float lse = m + logf(s);
    p[lane] = v0 - lse;
    p[lane + 32] = v1 - lse;
}

// ---------------- launch ----------------
extern "C" void kernel_launch(void* const* d_in, const int* in_sizes, int n_in,
                              void* d_out, int out_size) {
    const float* x        = (const float*)d_in[0];
    const float* edge_val = (const float*)d_in[1];
    const float* W_in     = (const float*)d_in[2];
    const float* b_in     = (const float*)d_in[3];
    const float* conv_W   = (const float*)d_in[4];
    const float* W_out    = (const float*)d_in[5];
    const float* b_out    = (const float*)d_in[6];
    const int*   edge_row = (const int*)d_in[7];
    const int*   edge_col = (const int*)d_in[8];
    float* out = (float*)d_out;

    float *hA, *hB, *x0_ptr;
    __nv_bfloat16 *xhi, *xlo, *mhi, *mlo, *winh, *winl, *wlh, *wll, *woh, *wol;
    cudaGetSymbolAddress((void**)&hA, g_hA);
    cudaGetSymbolAddress((void**)&hB, g_hB);
    cudaGetSymbolAddress((void**)&x0_ptr, g_x0);
    cudaGetSymbolAddress((void**)&xhi, g_xhi);
    cudaGetSymbolAddress((void**)&xlo, g_xlo);
    cudaGetSymbolAddress((void**)&mhi, g_mhi);
    cudaGetSymbolAddress((void**)&mlo, g_mlo);
    cudaGetSymbolAddress((void**)&winh, g_Winhi);
    cudaGetSymbolAddress((void**)&winl, g_Winlo);
    cudaGetSymbolAddress((void**)&wlh, g_Wlhi);
    cudaGetSymbolAddress((void**)&wll, g_Wllo);
    cudaGetSymbolAddress((void**)&woh, g_Wouthi);
    cudaGetSymbolAddress((void**)&wol, g_Woutlo);

    cudaFuncSetAttribute(mma_gemm_kernel, cudaFuncAttributeMaxDynamicSharedMemorySize, GEMM_SMEM);
    cudaFuncSetAttribute(fused_layer_kernel, cudaFuncAttributeMaxDynamicSharedMemorySize, FUSED_SMEM);

    // 1. CSR build + precision splits
    zero_cnt_kernel<<<(N_NODES + 255) / 256, 256>>>();
    count_kernel<<<(N_EDGES + 255) / 256, 256>>>(edge_row);
    scan_kernel<<<1, 1024>>>();
    scatter_kernel<<<(N_EDGES + 255) / 256, 256>>>(edge_row, edge_col, edge_val);
    split_x_kernel<<<(int)(((size_t)N_NODES * F_IN / 4 + 255) / 256), 256>>>(x);
    {
        int total = HID * F_IN + NLAYERS * HID * HID + NCLS * HID;
        conv_weights_kernel<<<(total + 255) / 256, 256>>>(W_in, conv_W, W_out);
    }

    // 2. input GEMM: hA = x0 = relu(x @ W_in + b_in)
    {
        dim3 grid(HID / BN, (N_NODES + BM - 1) / BM);
        mma_gemm_kernel<<<grid, 256, GEMM_SMEM>>>(
            xhi, xlo, F_IN, F_IN / BKC, winh, winl, b_in, hA, x0_ptr, HID, 1);
    }

    // 3. fused GCN2 layers (ping-pong h buffers)
    {
        const int fgrid = (N_NODES + FBM - 1) / FBM;
        float* bufs[2] = {hA, hB};
        for (int l = 0; l < NLAYERS; l++) {
            float beta = (float)log(0.5 / (double)(l + 1) + 1.0);
            fused_layer_kernel<<<fgrid, 512, FUSED_SMEM>>>(
                bufs[l & 1], bufs[(l + 1) & 1],
                wlh + (size_t)l * HID * HID, wll + (size_t)l * HID * HID,
                beta, l == NLAYERS - 1);
        }
    }

    // 4. output GEMM (MMA, bf16x3): logits = h @ W_out + b_out
    {
        dim3 grid(1, (N_NODES + BM - 1) / BM);
        mma_gemm_kernel<<<grid, 256, GEMM_SMEM>>>(
            mhi, mlo, HID, HID / BKC, woh, wol, b_out, out, nullptr, NCLS, 0);
    }

    // 5. log_softmax in place
    logsoftmax_kernel<<<(N_NODES + 7) / 8, 256>>>(out);
}

// round 8
// speedup vs baseline: 2.2230x; 1.2660x over previous
#include <cuda_runtime.h>
#include <cuda_bf16.h>
#include <cuda_fp16.h>
#include <math.h>
#include <stdint.h>

#define N_NODES 100000
#define N_EDGES 3200000
#define F_IN    512
#define HID     256
#define NCLS    64
#define NLAYERS 8
#define ALPHA   0.1f

// ---------------- device scratch (static, no allocations) ----------------
__device__ __half g_hfA[(size_t)N_NODES * HID];          // h ping (fp16, scaled 16^-l)
__device__ __half g_hfB[(size_t)N_NODES * HID];          // h pong (fp16, scaled)
__device__ float g_x0[(size_t)N_NODES * HID];
__device__ __nv_bfloat16 g_mhi[(size_t)N_NODES * HID];   // last-layer h hi (true scale)
__device__ __nv_bfloat16 g_mlo[(size_t)N_NODES * HID];   // last-layer h lo
__device__ __nv_bfloat16 g_xhi[(size_t)N_NODES * F_IN];
__device__ __nv_bfloat16 g_xlo[(size_t)N_NODES * F_IN];
__device__ __nv_bfloat16 g_Winhi[HID * F_IN];            // [n][k]
__device__ __nv_bfloat16 g_Winlo[HID * F_IN];
__device__ __nv_bfloat16 g_Wlhi[NLAYERS * HID * HID];    // [l][n][k]
__device__ __nv_bfloat16 g_Wllo[NLAYERS * HID * HID];
__device__ __nv_bfloat16 g_Wouthi[NCLS * HID];           // [n][k]
__device__ __nv_bfloat16 g_Woutlo[NCLS * HID];
__device__ int   g_rowptr[N_NODES + 1];
__device__ int   g_cnt[N_NODES];
__device__ int   g_colv[N_EDGES];
__device__ float g_valv[N_EDGES];

// ---------------- PTX helpers (arch-agnostic: sm_80+) ----------------
__device__ __forceinline__ uint32_t smem_u32(const void* p) {
    uint32_t a;
    asm("{ .reg .u64 t; cvta.to.shared.u64 t, %1; cvt.u32.u64 %0, t; }" : "=r"(a) : "l"(p));
    return a;
}
__device__ __forceinline__ void cp_async16(uint32_t dst, const void* src) {
    asm volatile("cp.async.cg.shared.global [%0], [%1], 16;" :: "r"(dst), "l"(src));
}
#define CP_COMMIT() asm volatile("cp.async.commit_group;" ::: "memory")
#define CP_WAIT0()  asm volatile("cp.async.wait_group 0;" ::: "memory")

__device__ __forceinline__ void ldmx4(uint32_t* r, uint32_t addr) {
    asm volatile("ldmatrix.sync.aligned.m8n8.x4.shared.b16 {%0,%1,%2,%3}, [%4];"
                 : "=r"(r[0]), "=r"(r[1]), "=r"(r[2]), "=r"(r[3]) : "r"(addr));
}
__device__ __forceinline__ void ldmx2(uint32_t* r, uint32_t addr) {
    asm volatile("ldmatrix.sync.aligned.m8n8.x2.shared.b16 {%0,%1}, [%2];"
                 : "=r"(r[0]), "=r"(r[1]) : "r"(addr));
}
__device__ __forceinline__ void mma16816(float* d, const uint32_t* a, const uint32_t* b) {
    asm volatile("mma.sync.aligned.m16n8k16.row.col.f32.bf16.bf16.f32 "
                 "{%0,%1,%2,%3}, {%4,%5,%6,%7}, {%8,%9}, {%0,%1,%2,%3};"
                 : "+f"(d[0]), "+f"(d[1]), "+f"(d[2]), "+f"(d[3])
                 : "r"(a[0]), "r"(a[1]), "r"(a[2]), "r"(a[3]), "r"(b[0]), "r"(b[1]));
}

// ---------------- CSR build ----------------
__global__ void zero_cnt_kernel() {
    int i = blockIdx.x * blockDim.x + threadIdx.x;
    if (i < N_NODES) g_cnt[i] = 0;
}
__global__ void count_kernel(const int* __restrict__ edge_row) {
    int e = blockIdx.x * blockDim.x + threadIdx.x;
    if (e < N_EDGES) atomicAdd(&g_cnt[edge_row[e]], 1);
}
__global__ void scan_kernel() {
    __shared__ int s[1024];
    const int t = threadIdx.x;
    const int CH = (N_NODES + 1023) / 1024;
    int begin = t * CH;
    int end = begin + CH; if (end > N_NODES) end = N_NODES;
    if (begin > N_NODES) begin = N_NODES;
    int sum = 0;
    for (int i = begin; i < end; i++) sum += g_cnt[i];
    s[t] = sum;
    __syncthreads();
    for (int off = 1; off < 1024; off <<= 1) {
        int v = (t >= off) ? s[t - off] : 0;
        __syncthreads();
        s[t] += v;
        __syncthreads();
    }
    int run = s[t] - sum;
    for (int i = begin; i < end; i++) {
        int c = g_cnt[i];
        g_rowptr[i] = run;
        run += c;
        g_cnt[i] = 0;
    }
    if (t == 1023) g_rowptr[N_NODES] = s[1023];
}
__global__ void scatter_kernel(const int* __restrict__ edge_row,
                               const int* __restrict__ edge_col,
                               const float* __restrict__ edge_val) {
    int e = blockIdx.x * blockDim.x + threadIdx.x;
    if (e < N_EDGES) {
        int r = edge_row[e];
        int pos = g_rowptr[r] + atomicAdd(&g_cnt[r], 1);
        g_colv[pos] = edge_col[e];
        g_valv[pos] = edge_val[e];
    }
}

// ---------------- conversions ----------------
__device__ __forceinline__ void split_bf16(float v, __nv_bfloat16& hi, __nv_bfloat16& lo) {
    hi = __float2bfloat16_rn(v);
    lo = __float2bfloat16_rn(v - __bfloat162float(hi));
}

__global__ void split_x_kernel(const float* __restrict__ x) {
    size_t i = (size_t)blockIdx.x * blockDim.x + threadIdx.x;
    size_t total = (size_t)N_NODES * F_IN / 4;
    if (i >= total) return;
    float4 v = ((const float4*)x)[i];
    __nv_bfloat16 h0, h1, h2, h3, l0, l1, l2, l3;
    split_bf16(v.x, h0, l0); split_bf16(v.y, h1, l1);
    split_bf16(v.z, h2, l2); split_bf16(v.w, h3, l3);
    __nv_bfloat162 ph0 = __halves2bfloat162(h0, h1), ph1 = __halves2bfloat162(h2, h3);
    __nv_bfloat162 pl0 = __halves2bfloat162(l0, l1), pl1 = __halves2bfloat162(l2, l3);
    ((uint2*)g_xhi)[i] = make_uint2(*(uint32_t*)&ph0, *(uint32_t*)&ph1);
    ((uint2*)g_xlo)[i] = make_uint2(*(uint32_t*)&pl0, *(uint32_t*)&pl1);
}

__global__ void conv_weights_kernel(const float* __restrict__ W_in,
                                    const float* __restrict__ conv_W,
                                    const float* __restrict__ W_out) {
    int i = blockIdx.x * blockDim.x + threadIdx.x;
    const int NIN = HID * F_IN;
    const int NL = NLAYERS * HID * HID;
    if (i < NIN) {
        int n = i / F_IN, k = i % F_IN;     // B[n][k] = W_in[k][n]
        __nv_bfloat16 hi, lo;
        split_bf16(W_in[(size_t)k * HID + n], hi, lo);
        g_Winhi[i] = hi; g_Winlo[i] = lo;
    } else if (i < NIN + NL) {
        int j = i - NIN;
        int l = j / (HID * HID);
        int r = j % (HID * HID);
        int n = r / HID, k = r % HID;       // B[l][n][k] = conv_W[l][k][n]
        __nv_bfloat16 hi, lo;
        split_bf16(conv_W[(size_t)l * HID * HID + (size_t)k * HID + n], hi, lo);
        g_Wlhi[j] = hi; g_Wllo[j] = lo;
    } else {
        int j = i - NIN - NL;
        if (j < NCLS * HID) {
            int n = j / HID, k = j % HID;   // B[n][k] = W_out[k][n]
            __nv_bfloat16 hi, lo;
            split_bf16(W_out[(size_t)k * NCLS + n], hi, lo);
            g_Wouthi[j] = hi; g_Woutlo[j] = lo;
        }
    }
}

// ============ fused layer: scaled-fp16 SpMM + mix + bf16 split (SMEM) + MMA GEMM ============
// h_in fp16 holds h_true * 16^-l; unscale = 16^l restores true units after the gather.
// h_out stores h_true * scale_out (= 16^-(l+1)). Last layer emits true-scale bf16 hi/lo.
#define FBM 64
#define AST 264                         // bf16 per A smem row (528B, conflict-free)
#define A_ELEMS (FBM * AST)             // 16896 bf16 per matrix
#define WSTRIDE 40
#define W_ELEMS (64 * WSTRIDE)          // 2560 bf16 per matrix per stage
#define W_BASE (2 * A_ELEMS)            // 33792
#define FUSED_SMEM ((W_BASE + 2 * 2 * W_ELEMS) * 2)   // 88064 bytes

__device__ __forceinline__ void acc_half8(float4& a, float4& b, float v, const uint4& u) {
    const __half2* p = (const __half2*)&u;
    float2 f0 = __half22float2(p[0]);
    float2 f1 = __half22float2(p[1]);
    float2 f2 = __half22float2(p[2]);
    float2 f3 = __half22float2(p[3]);
    a.x += v * f0.x; a.y += v * f0.y; a.z += v * f1.x; a.w += v * f1.y;
    b.x += v * f2.x; b.y += v * f2.y; b.z += v * f3.x; b.w += v * f3.y;
}

__global__ void __launch_bounds__(512, 2)
fused_layer_kernel(const __half* __restrict__ h_in, __half* __restrict__ h_out,
                   const __nv_bfloat16* __restrict__ Whi,
                   const __nv_bfloat16* __restrict__ Wlo,
                   float beta, float unscale, float scale_out, int last) {
    extern __shared__ __nv_bfloat16 sm[];
    const uint32_t smb = smem_u32(sm);
    const int tid = threadIdx.x;
    const int wid = tid >> 5, lane = tid & 31;
    const int row0 = blockIdx.x * FBM;

    __nv_bfloat16* Ahi_s = sm;
    __nv_bfloat16* Alo_s = sm + A_ELEMS;

    // ---------------- phase 1: scaled fp16 SpMM + mix + split into SMEM ----------------
    const uint4* hp = (const uint4*)h_in;   // 32 uint4 per row
    const float ua = (1.f - ALPHA) * unscale;  // restore true units: agg_true = acc * unscale
#pragma unroll
    for (int it = 0; it < FBM / 16; it++) {
        const int rl = it * 16 + wid;
        const int row = row0 + rl;
        float4 a = make_float4(0.f, 0.f, 0.f, 0.f);
        float4 b = make_float4(0.f, 0.f, 0.f, 0.f);
        float4 ma = a, mb = b;
        if (row < N_NODES) {
            const int start = g_rowptr[row];
            const int end = g_rowptr[row + 1];
            int e = start;
            for (; e + 3 < end; e += 4) {
                int c0 = g_colv[e], c1 = g_colv[e + 1], c2 = g_colv[e + 2], c3 = g_colv[e + 3];
                float v0 = g_valv[e], v1 = g_valv[e + 1], v2 = g_valv[e + 2], v3 = g_valv[e + 3];
                uint4 u0 = hp[(size_t)c0 * 32 + lane];
                uint4 u1 = hp[(size_t)c1 * 32 + lane];
                uint4 u2 = hp[(size_t)c2 * 32 + lane];
                uint4 u3 = hp[(size_t)c3 * 32 + lane];
                acc_half8(a, b, v0, u0);
                acc_half8(a, b, v1, u1);
                acc_half8(a, b, v2, u2);
                acc_half8(a, b, v3, u3);
            }
            for (; e < end; e++) {
                int c0 = g_colv[e];
                float v0 = g_valv[e];
                uint4 u0 = hp[(size_t)c0 * 32 + lane];
                acc_half8(a, b, v0, u0);
            }
            float4 xa = ((const float4*)g_x0)[(size_t)row * 64 + lane * 2];
            float4 xb = ((const float4*)g_x0)[(size_t)row * 64 + lane * 2 + 1];
            ma.x = ua * a.x + ALPHA * xa.x;
            ma.y = ua * a.y + ALPHA * xa.y;
            ma.z = ua * a.z + ALPHA * xa.z;
            ma.w = ua * a.w + ALPHA * xa.w;
            mb.x = ua * b.x + ALPHA * xb.x;
            mb.y = ua * b.y + ALPHA * xb.y;
            mb.z = ua * b.z + ALPHA * xb.z;
            mb.w = ua * b.w + ALPHA * xb.w;
        }
        // cols 8*lane..8*lane+7 -> 8 bf16 = one uint4 per matrix (true units)
        __nv_bfloat16 h0, h1, h2, h3, h4, h5, h6, h7;
        __nv_bfloat16 l0, l1, l2, l3, l4, l5, l6, l7;
        split_bf16(ma.x, h0, l0); split_bf16(ma.y, h1, l1);
        split_bf16(ma.z, h2, l2); split_bf16(ma.w, h3, l3);
        split_bf16(mb.x, h4, l4); split_bf16(mb.y, h5, l5);
        split_bf16(mb.z, h6, l6); split_bf16(mb.w, h7, l7);
        __nv_bfloat162 ph0 = __halves2bfloat162(h0, h1), ph1 = __halves2bfloat162(h2, h3);
        __nv_bfloat162 ph2 = __halves2bfloat162(h4, h5), ph3 = __halves2bfloat162(h6, h7);
        __nv_bfloat162 pl0 = __halves2bfloat162(l0, l1), pl1 = __halves2bfloat162(l2, l3);
        __nv_bfloat162 pl2 = __halves2bfloat162(l4, l5), pl3 = __halves2bfloat162(l6, l7);
        *(uint4*)(Ahi_s + rl * AST + lane * 8) =
            make_uint4(*(uint32_t*)&ph0, *(uint32_t*)&ph1, *(uint32_t*)&ph2, *(uint32_t*)&ph3);
        *(uint4*)(Alo_s + rl * AST + lane * 8) =
            make_uint4(*(uint32_t*)&pl0, *(uint32_t*)&pl1, *(uint32_t*)&pl2, *(uint32_t*)&pl3);
    }
    __syncthreads();

    // ---------------- phase 2: GEMM mix @ W^T + epilogue ----------------
    const int wm = wid >> 2;        // 0..3 : 16-row tile
    const int wn = wid & 3;         // 0..3 : 16-col tile within 64
    const float wmix = 1.f - beta;

    auto load_w = [&](int nt4, int c, int s) {
        int idx = tid & 255;
        int r = idx >> 2, v = idx & 3;
        const __nv_bfloat16* src = (tid < 256 ? Whi : Wlo)
                                 + (size_t)(nt4 * 64 + r) * HID + c * 32 + v * 8;
        uint32_t off = W_BASE + s * (2 * W_ELEMS) + (tid < 256 ? 0 : W_ELEMS)
                     + r * WSTRIDE + v * 8;
        cp_async16(smb + off * 2, src);
    };

    for (int nt4 = 0; nt4 < 4; nt4++) {
        float acc[2][4];
#pragma unroll
        for (int i = 0; i < 2; i++)
#pragma unroll
            for (int j = 0; j < 4; j++) acc[i][j] = 0.f;

        load_w(nt4, 0, 0);
        CP_COMMIT();
        for (int c = 0; c < 8; c++) {
            CP_WAIT0();
            __syncthreads();
            if (c + 1 < 8) { load_w(nt4, c + 1, (c + 1) & 1); CP_COMMIT(); }
            const uint32_t wsb = smb + (W_BASE + (c & 1) * (2 * W_ELEMS)) * 2;
#pragma unroll
            for (int ks = 0; ks < 2; ks++) {
                uint32_t ah[4], al[4], bh[2][2], bl[2][2];
                uint32_t aAddr = smb + (uint32_t)((wm * 16 + (lane & 15)) * AST
                                + c * 32 + ks * 16 + (lane >> 4) * 8) * 2;
                ldmx4(ah, aAddr);
                ldmx4(al, aAddr + A_ELEMS * 2);
#pragma unroll
                for (int nt = 0; nt < 2; nt++) {
                    uint32_t bAddr = wsb + (uint32_t)((wn * 16 + nt * 8 + (lane & 7)) * WSTRIDE
                                    + ks * 16 + ((lane >> 3) & 1) * 8) * 2;
                    ldmx2(bh[nt], bAddr);
                    ldmx2(bl[nt], bAddr + W_ELEMS * 2);
                }
#pragma unroll
                for (int nt = 0; nt < 2; nt++) {
                    mma16816(acc[nt], ah, bh[nt]);
                    mma16816(acc[nt], ah, bl[nt]);
                    mma16816(acc[nt], al, bh[nt]);
                }
            }
            __syncthreads();
        }

        // epilogue for this 64-col tile
        const int r_loc0 = wm * 16 + (lane >> 2);
#pragma unroll
        for (int half = 0; half < 2; half++) {
            int rl = r_loc0 + half * 8;
            int grow = row0 + rl;
            if (grow >= N_NODES) continue;
#pragma unroll
            for (int nt = 0; nt < 2; nt++) {
                int gc = nt4 * 64 + wn * 16 + nt * 8 + (lane & 3) * 2;
                uint32_t hiw = *(uint32_t*)(Ahi_s + rl * AST + gc);
                uint32_t low = *(uint32_t*)(Alo_s + rl * AST + gc);
                __nv_bfloat162 hv = *(__nv_bfloat162*)&hiw;
                __nv_bfloat162 lv = *(__nv_bfloat162*)&low;
                float m0 = __bfloat162float(hv.x) + __bfloat162float(lv.x);
                float m1 = __bfloat162float(hv.y) + __bfloat162float(lv.y);
                float v0 = fmaxf(wmix * m0 + beta * acc[nt][half * 2 + 0], 0.f);
                float v1 = fmaxf(wmix * m1 + beta * acc[nt][half * 2 + 1], 0.f);
                if (!last) {
                    __half2 o = __floats2half2_rn(v0 * scale_out, v1 * scale_out);
                    *(uint32_t*)&h_out[(size_t)grow * HID + gc] = *(uint32_t*)&o;
                } else {
                    __nv_bfloat16 hh0, hl0, hh1, hl1;
                    split_bf16(v0, hh0, hl0);
                    split_bf16(v1, hh1, hl1);
                    __nv_bfloat162 ph = __halves2bfloat162(hh0, hh1);
                    __nv_bfloat162 pl = __halves2bfloat162(hl0, hl1);
                    *(uint32_t*)&g_mhi[(size_t)grow * HID + gc] = *(uint32_t*)&ph;
                    *(uint32_t*)&g_mlo[(size_t)grow * HID + gc] = *(uint32_t*)&pl;
                }
            }
        }
        __syncthreads();
    }
}

// ---------------- bf16x3 MMA GEMM (input + output layers) ----------------
#define BM 128
#define BN 64
#define BKC 32
#define ASTRIDE 40
#define A_STG (BM * ASTRIDE)
#define B_STG (BN * ASTRIDE)
#define STG_ELEMS (2 * A_STG + 2 * B_STG)
#define GEMM_SMEM (2 * STG_ELEMS * 2)

__global__ void __launch_bounds__(256, 2)
mma_gemm_kernel(const __nv_bfloat16* __restrict__ Ahi, const __nv_bfloat16* __restrict__ Alo,
                int lda, int chunks,
                const __nv_bfloat16* __restrict__ Bhi, const __nv_bfloat16* __restrict__ Blo,
                const float* __restrict__ bias,
                float* __restrict__ outf, __half* __restrict__ outh,
                int ldc, int do_relu) {
    extern __shared__ __nv_bfloat16 smg[];
    const uint32_t smb = smem_u32(smg);
    const int tid = threadIdx.x;
    const int row0 = blockIdx.y * BM;
    const int n0 = blockIdx.x * BN;
    const int wid = tid >> 5, lane = tid & 31;
    const int wm = wid >> 1, wn = wid & 1;

    auto load_chunk = [&](int c, int s) {
        const int base = s * STG_ELEMS;
        const __nv_bfloat16* ah = Ahi + (size_t)c * BKC;
        const __nv_bfloat16* al = Alo + (size_t)c * BKC;
#pragma unroll
        for (int i = 0; i < 2; i++) {
            int idx = tid + i * 256;
            int r = idx >> 2, v = idx & 3;
            int rg = row0 + r; if (rg >= N_NODES) rg = N_NODES - 1;
            uint32_t d = smb + (uint32_t)(base + r * ASTRIDE + v * 8) * 2;
            cp_async16(d, ah + (size_t)rg * lda + v * 8);
            cp_async16(d + A_STG * 2, al + (size_t)rg * lda + v * 8);
        }
        {
            int r = tid >> 2, v = tid & 3;
            uint32_t d = smb + (uint32_t)(base + 2 * A_STG + r * ASTRIDE + v * 8) * 2;
            size_t off = (size_t)(n0 + r) * lda + (size_t)c * BKC + v * 8;
            cp_async16(d, Bhi + off);
            cp_async16(d + B_STG * 2, Blo + off);
        }
    };

    float acc[2][4][4];
#pragma unroll
    for (int i = 0; i < 2; i++)
#pragma unroll
        for (int j = 0; j < 4; j++)
#pragma unroll
            for (int k = 0; k < 4; k++) acc[i][j][k] = 0.f;

    load_chunk(0, 0);
    CP_COMMIT();

    for (int c = 0; c < chunks; c++) {
        CP_WAIT0();
        __syncthreads();
        if (c + 1 < chunks) {
            load_chunk(c + 1, (c + 1) & 1);
            CP_COMMIT();
        }
        const int base = (c & 1) * STG_ELEMS;
        uint32_t aAddr = smb + (uint32_t)(base + (wm * 32 + (lane & 15)) * ASTRIDE + (lane >> 4) * 8) * 2;
        uint32_t bAddr = smb + (uint32_t)(base + 2 * A_STG + (wn * 32 + (lane & 7)) * ASTRIDE + ((lane >> 3) & 1) * 8) * 2;
#pragma unroll
        for (int ks = 0; ks < 2; ks++) {
            uint32_t ah[2][4], al[2][4], bh[4][2], bl[4][2];
#pragma unroll
            for (int mt = 0; mt < 2; mt++) {
                uint32_t addr = aAddr + (uint32_t)mt * (16 * ASTRIDE * 2) + ks * 32;
                ldmx4(ah[mt], addr);
                ldmx4(al[mt], addr + A_STG * 2);
            }
#pragma unroll
            for (int nt = 0; nt < 4; nt++) {
                uint32_t addr = bAddr + (uint32_t)nt * (8 * ASTRIDE * 2) + ks * 32;
                ldmx2(bh[nt], addr);
                ldmx2(bl[nt], addr + B_STG * 2);
            }
#pragma unroll
            for (int mt = 0; mt < 2; mt++)
#pragma unroll
                for (int nt = 0; nt < 4; nt++) {
                    mma16816(acc[mt][nt], ah[mt], bh[nt]);
                    mma16816(acc[mt][nt], ah[mt], bl[nt]);
                    mma16816(acc[mt][nt], al[mt], bh[nt]);
                }
        }
        __syncthreads();
    }

    const int r_base = row0 + wm * 32 + (lane >> 2);
    const int c_base = n0 + wn * 32 + (lane & 3) * 2;
#pragma unroll
    for (int mt = 0; mt < 2; mt++)
#pragma unroll
        for (int half = 0; half < 2; half++) {
            int r = r_base + mt * 16 + half * 8;
            if (r >= N_NODES) continue;
#pragma unroll
            for (int nt = 0; nt < 4; nt++) {
                int cc = c_base + nt * 8;
                float v0 = acc[mt][nt][half * 2 + 0] + bias[cc];
                float v1 = acc[mt][nt][half * 2 + 1] + bias[cc + 1];
                if (do_relu) { v0 = fmaxf(v0, 0.f); v1 = fmaxf(v1, 0.f); }
                if (outf) *(float2*)&outf[(size_t)r * ldc + cc] = make_float2(v0, v1);
                if (outh) {
                    __half2 o = __floats2half2_rn(v0, v1);
                    *(uint32_t*)&outh[(size_t)r * ldc + cc] = *(uint32_t*)&o;
                }
            }
        }
}

// ---------------- log_softmax ----------------
__global__ void logsoftmax_kernel(float* __restrict__ logits) {
    const int lane = threadIdx.x & 31;
    const int wid = threadIdx.x >> 5;
    const int row = blockIdx.x * (blockDim.x >> 5) + wid;
    if (row >= N_NODES) return;
    float* p = logits + (size_t)row * NCLS;
    float v0 = p[lane];
    float v1 = p[lane + 32];
    float m = fmaxf(v0, v1);
#pragma unroll
    for (int off = 16; off > 0; off >>= 1)
        m = fmaxf(m, __shfl_xor_sync(0xffffffffu, m, off));
    float s = expf(v0 - m) + expf(v1 - m);
#pragma unroll
    for (int off = 16; off > 0; off >>= 1)
        s += __shfl_xor_sync(0xffffffffu, s, off);
    float lse = m + logf(s);
    p[lane] = v0 - lse;
    p[lane + 32] = v1 - lse;
}

// ---------------- launch ----------------
extern "C" void kernel_launch(void* const* d_in, const int* in_sizes, int n_in,
                              void* d_out, int out_size) {
    const float* x        = (const float*)d_in[0];
    const float* edge_val = (const float*)d_in[1];
    const float* W_in     = (const float*)d_in[2];
    const float* b_in     = (const float*)d_in[3];
    const float* conv_W   = (const float*)d_in[4];
    const float* W_out    = (const float*)d_in[5];
    const float* b_out    = (const float*)d_in[6];
    const int*   edge_row = (const int*)d_in[7];
    const int*   edge_col = (const int*)d_in[8];
    float* out = (float*)d_out;

    float *x0_ptr;
    __half *hfA, *hfB;
    __nv_bfloat16 *xhi, *xlo, *mhi, *mlo, *winh, *winl, *wlh, *wll, *woh, *wol;
    cudaGetSymbolAddress((void**)&hfA, g_hfA);
    cudaGetSymbolAddress((void**)&hfB, g_hfB);
    cudaGetSymbolAddress((void**)&x0_ptr, g_x0);
    cudaGetSymbolAddress((void**)&xhi, g_xhi);
    cudaGetSymbolAddress((void**)&xlo, g_xlo);
    cudaGetSymbolAddress((void**)&mhi, g_mhi);
    cudaGetSymbolAddress((void**)&mlo, g_mlo);
    cudaGetSymbolAddress((void**)&winh, g_Winhi);
    cudaGetSymbolAddress((void**)&winl, g_Winlo);
    cudaGetSymbolAddress((void**)&wlh, g_Wlhi);
    cudaGetSymbolAddress((void**)&wll, g_Wllo);
    cudaGetSymbolAddress((void**)&woh, g_Wouthi);
    cudaGetSymbolAddress((void**)&wol, g_Woutlo);

    cudaFuncSetAttribute(mma_gemm_kernel, cudaFuncAttributeMaxDynamicSharedMemorySize, GEMM_SMEM);
    cudaFuncSetAttribute(fused_layer_kernel, cudaFuncAttributeMaxDynamicSharedMemorySize, FUSED_SMEM);

    // 1. CSR build + precision splits
    zero_cnt_kernel<<<(N_NODES + 255) / 256, 256>>>();
    count_kernel<<<(N_EDGES + 255) / 256, 256>>>(edge_row);
    scan_kernel<<<1, 1024>>>();
    scatter_kernel<<<(N_EDGES + 255) / 256, 256>>>(edge_row, edge_col, edge_val);
    split_x_kernel<<<(int)(((size_t)N_NODES * F_IN / 4 + 255) / 256), 256>>>(x);
    {
        int total = HID * F_IN + NLAYERS * HID * HID + NCLS * HID;
        conv_weights_kernel<<<(total + 255) / 256, 256>>>(W_in, conv_W, W_out);
    }

    // 2. input GEMM: hA(fp16, scale 16^0=1) = x0(fp32) = relu(x @ W_in + b_in)
    {
        dim3 grid(HID / BN, (N_NODES + BM - 1) / BM);
        mma_gemm_kernel<<<grid, 256, GEMM_SMEM>>>(
            xhi, xlo, F_IN, F_IN / BKC, winh, winl, b_in, x0_ptr, hfA, HID, 1);
    }

    // 3. fused GCN2 layers (ping-pong scaled fp16 h buffers)
    {
        const int fgrid = (N_NODES + FBM - 1) / FBM;
        __half* bufs[2] = {hfA, hfB};
        double sc = 1.0;                        // 16^l
        for (int l = 0; l < NLAYERS; l++) {
            float beta = (float)log(0.5 / (double)(l + 1) + 1.0);
            float unscale = (float)sc;          // restore true units after gather
            float scale_out = (float)(1.0 / (sc * 16.0));  // store h_true * 16^-(l+1)
            fused_layer_kernel<<<fgrid, 512, FUSED_SMEM>>>(
                bufs[l & 1], bufs[(l + 1) & 1],
                wlh + (size_t)l * HID * HID, wll + (size_t)l * HID * HID,
                beta, unscale, scale_out, l == NLAYERS - 1);
            sc *= 16.0;
        }
    }

    // 4. output GEMM (MMA, bf16x3): logits = h @ W_out + b_out
    {
        dim3 grid(1, (N_NODES + BM - 1) / BM);
        mma_gemm_kernel<<<grid, 256, GEMM_SMEM>>>(
            mhi, mlo, HID, HID / BKC, woh, wol, b_out, out, nullptr, NCLS, 0);
    }

    // 5. log_softmax in place
    logsoftmax_kernel<<<(N_NODES + 7) / 8, 256>>>(out);
}